// round 1
// baseline (speedup 1.0000x reference)
#include <cuda_runtime.h>
#include <cstdint>
#include <math.h>

#define Bq 128
#define Tq 512
#define Cq 100
#define Eq 64
#define Hq 256
#define G7 1792   // 7*H
#define KIN 320   // E+H

// ---- scratch (device globals; no allocation in kernel_launch) ----
static __device__ float g_r[(size_t)Bq * Tq * Eq];          // 16.8 MB   rec_input
static __device__ float g_gin[(size_t)Bq * Tq * G7];        // 470 MB    input-side gates (+bias)
static __device__ float g_h[2][16][8][Hq];                  // ping-pong h_d exchange

__device__ __forceinline__ float sigmf_(float x) { return 1.f / (1.f + expf(-x)); }
__device__ __forceinline__ float softplusf_(float x) {
    return fmaxf(x, 0.f) + log1pf(expf(-fabsf(x)));
}

// ---------------------------------------------------------------------------
// K1: rec_input[b,t,e] = (marks[b,t,:] @ W_emb[:,e]) / max(sum(marks),1)
// ---------------------------------------------------------------------------
__global__ __launch_bounds__(128) void k_embed(const float* __restrict__ marks,
                                               const float* __restrict__ Wemb) {
    int bt = blockIdx.x;
    __shared__ float sm[Cq];
    int tid = threadIdx.x;
    if (tid < Cq) sm[tid] = marks[(size_t)bt * Cq + tid];
    __syncthreads();
    if (tid < Eq) {
        float cnt = 0.f, s = 0.f;
        #pragma unroll
        for (int c = 0; c < Cq; c++) {
            float m = sm[c];
            cnt += m;
            s = fmaf(m, Wemb[c * Eq + tid], s);
        }
        g_r[(size_t)bt * Eq + tid] = s / fmaxf(cnt, 1.f);
    }
}

// ---------------------------------------------------------------------------
// K2: g_gin[bt, j] = g_r[bt,:] @ W_cell[j, 0:64]^T + b_cell[j]
// tile: 64 bt-rows x 128 j-cols, K=64, thread micro-tile 4x8
// ---------------------------------------------------------------------------
__global__ __launch_bounds__(256) void k_gin(const float* __restrict__ Wc,
                                             const float* __restrict__ bc) {
    __shared__ float As[64 * 68];    // As[k*68 + row]
    __shared__ float Bs[64 * 132];   // Bs[k*132 + col]
    int tid = threadIdx.x;
    int row0 = blockIdx.x * 64, col0 = blockIdx.y * 128;

    #pragma unroll
    for (int i = 0; i < 16; i++) {
        int idx = i * 256 + tid;
        int row = idx >> 6, k = idx & 63;
        As[k * 68 + row] = g_r[(size_t)(row0 + row) * Eq + k];
    }
    #pragma unroll
    for (int i = 0; i < 32; i++) {
        int idx = i * 256 + tid;
        int col = idx >> 6, k = idx & 63;
        Bs[k * 132 + col] = Wc[(size_t)(col0 + col) * KIN + k];
    }
    __syncthreads();

    int tx = tid & 15, ty = tid >> 4;
    float acc[4][8];
    #pragma unroll
    for (int i = 0; i < 4; i++)
        #pragma unroll
        for (int jx = 0; jx < 8; jx++) acc[i][jx] = 0.f;

    #pragma unroll 4
    for (int k = 0; k < 64; k++) {
        float4 a  = *(const float4*)&As[k * 68 + ty * 4];
        float4 b0 = *(const float4*)&Bs[k * 132 + tx * 8];
        float4 b1 = *(const float4*)&Bs[k * 132 + tx * 8 + 4];
        float av[4] = {a.x, a.y, a.z, a.w};
        float bv[8] = {b0.x, b0.y, b0.z, b0.w, b1.x, b1.y, b1.z, b1.w};
        #pragma unroll
        for (int i = 0; i < 4; i++)
            #pragma unroll
            for (int jx = 0; jx < 8; jx++)
                acc[i][jx] = fmaf(av[i], bv[jx], acc[i][jx]);
    }

    float bb[8];
    #pragma unroll
    for (int jx = 0; jx < 8; jx++) bb[jx] = bc[col0 + tx * 8 + jx];

    #pragma unroll
    for (int i = 0; i < 4; i++) {
        size_t base = (size_t)(row0 + ty * 4 + i) * G7 + col0 + tx * 8;
        float4 o0 = {acc[i][0] + bb[0], acc[i][1] + bb[1], acc[i][2] + bb[2], acc[i][3] + bb[3]};
        float4 o1 = {acc[i][4] + bb[4], acc[i][5] + bb[5], acc[i][6] + bb[6], acc[i][7] + bb[7]};
        *(float4*)&g_gin[base]     = o0;
        *(float4*)&g_gin[base + 4] = o1;
    }
}

// ---------------------------------------------------------------------------
// K3: initial state -> out[b,0,:] and g_h[0]
// init chunks: h_d, c_d, c_bar, c, delta, o ; state0 = [hd,o,cbar,c,delta,cd]
// ---------------------------------------------------------------------------
__global__ __launch_bounds__(256) void k_init(const float* __restrict__ init,
                                              float* __restrict__ out) {
    int b = blockIdx.x, k = threadIdx.x;
    float s0 = init[k], s1 = init[Hq + k], s2 = init[2 * Hq + k];
    float s3 = init[3 * Hq + k], s4 = init[4 * Hq + k], s5 = init[5 * Hq + k];
    float hd0 = tanhf(s0), cd0 = tanhf(s1), cb0 = tanhf(s2), c0 = tanhf(s3);
    float d0 = softplusf_(s4), o0 = sigmf_(s5);
    size_t base = (size_t)b * (Tq + 1) * (6 * Hq);
    out[base + 0 * Hq + k] = hd0;
    out[base + 1 * Hq + k] = o0;
    out[base + 2 * Hq + k] = cb0;
    out[base + 3 * Hq + k] = c0;
    out[base + 4 * Hq + k] = d0;
    out[base + 5 * Hq + k] = cd0;
    g_h[0][b >> 3][b & 7][k] = hd0;
}

// ---------------------------------------------------------------------------
// K4: sequential recurrence. Cluster of 8 CTAs per batch-group of 8.
//   rank r owns hidden slice j in [r*32, r*32+32) across all 7 gates:
//   224 weight cols x 256 K, fp32, resident in SMEM (stride 225, conflict-free).
//   thread (warp g, lane jj) owns batch group*8+g, hidden index r*32+jj.
//   h_d exchanged via L2 (ldcg/stcg) + barrier.cluster per step (double buffer).
// ---------------------------------------------------------------------------
__global__ void __cluster_dims__(8, 1, 1) __launch_bounds__(256, 1)
k_recur(const float* __restrict__ Wc, const float* __restrict__ ts,
        const float* __restrict__ init, float* __restrict__ out) {
    extern __shared__ float sh[];
    float* Ws = sh;                 // [256][225]  Ws[k*225 + c], c = gate*32+jj
    float* hs = sh + 256 * 225;     // [8][32]     staged h chunk

    int tid = threadIdx.x;
    int g = tid >> 5, jj = tid & 31;
    int rank = blockIdx.x & 7, group = blockIdx.x >> 3;
    int b = group * 8 + g;
    int j = rank * 32 + jj;

    // load recurrent weight slice: coalesced LDG (k = tid), conflict-free STS
    for (int c = 0; c < 224; c++) {
        int gate = c >> 5, cj = c & 31;
        int row = gate * Hq + rank * 32 + cj;            // row in [0,1792)
        Ws[tid * 225 + c] = Wc[(size_t)row * KIN + Eq + tid];
    }

    float c_st  = tanhf(init[3 * Hq + j]);
    float cb_st = tanhf(init[2 * Hq + j]);
    __syncthreads();

    int hidx = (tid >> 5) * Hq + (tid & 31);

    for (int t = 0; t < Tq; t++) {
        int buf = t & 1;
        const float* hsrc = &g_h[buf][group][0][0];

        // prefetch input-side gates (+bias) and timestamps
        size_t gbase = ((size_t)b * Tq + t) * (size_t)G7 + j;
        float a0 = __ldcs(&g_gin[gbase + 0 * Hq]);
        float a1 = __ldcs(&g_gin[gbase + 1 * Hq]);
        float a2 = __ldcs(&g_gin[gbase + 2 * Hq]);
        float a3 = __ldcs(&g_gin[gbase + 3 * Hq]);
        float a4 = __ldcs(&g_gin[gbase + 4 * Hq]);
        float a5 = __ldcs(&g_gin[gbase + 5 * Hq]);
        float a6 = __ldcs(&g_gin[gbase + 6 * Hq]);
        float tcur  = ts[b * Tq + t];
        float tprev = (t > 0) ? ts[b * Tq + t - 1] : 0.f;

        float acc0 = 0.f, acc1 = 0.f, acc2 = 0.f, acc3 = 0.f;
        float acc4 = 0.f, acc5 = 0.f, acc6 = 0.f;

        float hpre = __ldcg(&hsrc[hidx]);   // chunk 0 prefetch
        #pragma unroll 1
        for (int ch = 0; ch < 8; ch++) {
            __syncthreads();
            hs[tid] = hpre;
            __syncthreads();
            if (ch < 7) hpre = __ldcg(&hsrc[hidx + (ch + 1) * 32]);
            #pragma unroll
            for (int kk = 0; kk < 32; kk++) {
                float h = hs[(g << 5) + kk];
                const float* w = &Ws[(ch * 32 + kk) * 225 + jj];
                acc0 = fmaf(w[0],   h, acc0);
                acc1 = fmaf(w[32],  h, acc1);
                acc2 = fmaf(w[64],  h, acc2);
                acc3 = fmaf(w[96],  h, acc3);
                acc4 = fmaf(w[128], h, acc4);
                acc5 = fmaf(w[160], h, acc5);
                acc6 = fmaf(w[192], h, acc6);
            }
        }

        a0 += acc0; a1 += acc1; a2 += acc2; a3 += acc3;
        a4 += acc4; a5 += acc5; a6 += acc6;

        float gi  = sigmf_(a0);
        float gf  = sigmf_(a1);
        float gz  = tanhf(a2);
        float go  = sigmf_(a3);
        float gib = sigmf_(a4);
        float gfb = sigmf_(a5);
        float gd  = softplusf_(a6);
        float dt  = tcur - tprev;

        float ct  = gf * c_st + gi * gz;
        float cbt = gfb * cb_st + gib * gz;
        float cdt = cbt + (ct - cbt) * expf(-gd * dt);
        float hdt = go * tanhf(cdt);

        size_t ob = ((size_t)b * (Tq + 1) + t + 1) * (size_t)(6 * Hq) + j;
        out[ob + 0 * Hq] = hdt;
        out[ob + 1 * Hq] = go;
        out[ob + 2 * Hq] = cbt;
        out[ob + 3 * Hq] = ct;
        out[ob + 4 * Hq] = gd;
        out[ob + 5 * Hq] = cdt;

        c_st = ct; cb_st = cbt;

        __stcg(&g_h[buf ^ 1][group][g][j], hdt);

        // cluster barrier: release h writes / acquire peers' h for next step
        asm volatile("barrier.cluster.arrive.aligned;" ::: "memory");
        asm volatile("barrier.cluster.wait.aligned;" ::: "memory");
    }
}

// ---------------------------------------------------------------------------
extern "C" void kernel_launch(void* const* d_in, const int* in_sizes, int n_in,
                              void* d_out, int out_size) {
    const float* marks = (const float*)d_in[0];
    const float* ts    = (const float*)d_in[1];
    const float* Wemb  = (const float*)d_in[2];
    const float* Wc    = (const float*)d_in[3];
    const float* bc    = (const float*)d_in[4];
    const float* init  = (const float*)d_in[5];
    float* out = (float*)d_out;

    k_embed<<<Bq * Tq, 128>>>(marks, Wemb);
    k_gin<<<dim3((Bq * Tq) / 64, G7 / 128), 256>>>(Wc, bc);
    k_init<<<Bq, 256>>>(init, out);

    const int SMEM = (256 * 225 + 256) * sizeof(float);   // 231,424 B
    cudaFuncSetAttribute(k_recur, cudaFuncAttributeMaxDynamicSharedMemorySize, SMEM);
    k_recur<<<128, 256, SMEM>>>(Wc, ts, init, out);
}